// round 15
// baseline (speedup 1.0000x reference)
#include <cuda_runtime.h>
#include <math.h>

#define NUMP 53149
#define NUMK 68
#define KPCA 80
#define BB   16
#define HIMG 640
#define WIMG 360
#define NPIX (HIMG*WIMG)          // 230400
#define ROWS (3*NUMP)             // 159447

// output layout (float32 concat of the returned tuple)
#define OUT_LK   0
#define OUT_LK1  1
#define OUT_LREG 2
#define OUT_LD   3
#define OUT_R1   4                 // B*9 = 144
#define OUT_T    148               // B*3 = 48
#define OUT_PK2  196               // B*68*2 = 2176
#define OUT_MASK 2372              // B*NPIX
#define OUT_PRED (2372 + BB*NPIX)  // B*NPIX

__device__ float          g_points0[ROWS];
__device__ unsigned char  g_occ[BB*NPIX];
__device__ float          g_coef[KPCA];
__device__ float          g_R1[BB*9];
__device__ float          g_y26574[BB];
__device__ double         g_sum[BB];
__device__ int            g_cnt[BB];
__device__ float          g_dval;

// correctly-rounded f32 trig (verified: R1 bit-exact with these)
__device__ __forceinline__ float sinf_cr(float x) { return (float)sin((double)x); }
__device__ __forceinline__ float cosf_cr(float x) { return (float)cos((double)x); }

// asc-k FMA dot from zero — Eigen gemm chain (verified exact for R1 3x3s;
// hypothesis: also the lowering of the LARGE pts transform einsum)
__device__ __forceinline__ float dot3_fma_asc(float a0, float a1, float a2,
                                              float b0, float b1, float b2)
{
    return fmaf(a2, b2, fmaf(a1, b1, __fmul_rn(a0, b0)));
}

// nofma LEFT-assoc (k0+k1)+k2 — naive loop emitter chain
// (VERIFIED bit-exact for the small pk path via out6 == 0)
__device__ __forceinline__ float dot3_nofma_left(float a0, float a1, float a2,
                                                 float b0, float b1, float b2)
{
    return __fadd_rn(__fadd_rn(__fmul_rn(a0, b0), __fmul_rn(a1, b1)),
                     __fmul_rn(a2, b2));
}

// VERIFIED projection: nofma numerators + RECIP-MUL divide
__device__ __forceinline__ void project_recip_nofma(float qx, float qy, float qz,
                                                    float& x, float& y)
{
    float pz  = -qz;
    float inv = __frcp_rn(pz);
    float ax  = __fadd_rn(__fmul_rn(qx, 436.16f), __fmul_rn(pz, 179.22f));
    float ay  = __fadd_rn(__fmul_rn(qy, 436.16f), __fmul_rn(pz, 320.08f));
    x = __fmul_rn(ax, inv);
    y = __fmul_rn(ay, inv);
}

// ---------------------------------------------------------------------------
// K0: zero occupancy map; compute coef, R1 (bit-exact), loss_reg; T; parse d
// ---------------------------------------------------------------------------
__global__ void k_init(const float* __restrict__ variance,
                       const float* __restrict__ param,
                       const float* __restrict__ R,
                       const float* __restrict__ T,
                       const unsigned* __restrict__ dptr,
                       float* __restrict__ out)
{
    int gid = blockIdx.x * blockDim.x + threadIdx.x;
    if (gid < (BB*NPIX)/16) ((uint4*)g_occ)[gid] = make_uint4(0u,0u,0u,0u);

    if (blockIdx.x == 0) {
        int t = threadIdx.x;
        if (t < KPCA) g_coef[t] = __fmul_rn(param[t], sqrtf(variance[t]));
        if (t >= 128 && t < 128 + BB) {
            int b = t - 128;
            float ax = R[b*3+0], ay = R[b*3+1], az = R[b*3+2];
            float sx = sinf_cr(ax), cx = cosf_cr(ax);
            float sy = sinf_cr(ay), cy = cosf_cr(ay);
            float sz = sinf_cr(az), cz = cosf_cr(az);
            float Rz[9] = { cz, -sz, 0.f,  sz,  cz, 0.f,  0.f, 0.f, 1.f };
            float Ry[9] = { cy, 0.f,  sy,  0.f, 1.f, 0.f, -sy, 0.f,  cy };
            float Rx[9] = { 1.f, 0.f, 0.f, 0.f,  cx, -sx,  0.f,  sx,  cx };
            float M1[9], r[9];
            #pragma unroll
            for (int i = 0; i < 3; ++i)
                #pragma unroll
                for (int j = 0; j < 3; ++j)
                    M1[i*3+j] = dot3_fma_asc(Rz[i*3+0], Rz[i*3+1], Rz[i*3+2],
                                             Ry[0*3+j], Ry[1*3+j], Ry[2*3+j]);
            #pragma unroll
            for (int i = 0; i < 3; ++i)
                #pragma unroll
                for (int j = 0; j < 3; ++j)
                    r[i*3+j] = dot3_fma_asc(M1[i*3+0], M1[i*3+1], M1[i*3+2],
                                            Rx[0*3+j], Rx[1*3+j], Rx[2*3+j]);
            #pragma unroll
            for (int i = 0; i < 9; ++i) {
                g_R1[b*9+i] = r[i];
                out[OUT_R1 + b*9 + i] = r[i];
            }
            g_sum[b] = 0.0;
            g_cnt[b] = 0;
        }
        if (t >= 160 && t < 160 + BB*3) out[OUT_T + (t - 160)] = T[t - 160];
        if (t == 224) {
            double s = 0.0;
            for (int i = 0; i < KPCA; ++i) { double p = (double)param[i]; s += p*p; }
            out[OUT_LREG] = (float)(s / (double)KPCA);
        }
        if (t == 225) {
            unsigned raw = *dptr;              // works for int32(100) or float32(100.f)
            g_dval = (raw == 100u) ? 100.0f : __uint_as_float(raw);
        }
    }
}

// ---------------------------------------------------------------------------
// K1: points0 = mean + pca @ coef ; thread per row, float4 loads (coalesced)
//     (empirically verified: reduce-order variants produce identical outputs)
// ---------------------------------------------------------------------------
__global__ void k_points0(const float* __restrict__ mean,
                          const float* __restrict__ pca)
{
    __shared__ float4 sc[KPCA/4];
    int t = threadIdx.x;
    if (t < KPCA/4) sc[t] = ((const float4*)g_coef)[t];
    __syncthreads();

    int r = blockIdx.x * blockDim.x + t;
    if (r >= ROWS) return;

    const float4* row = (const float4*)(pca + (size_t)r * KPCA);
    float s0 = 0.f, s1 = 0.f, s2 = 0.f, s3 = 0.f;
    #pragma unroll
    for (int j = 0; j < KPCA/4; ++j) {
        float4 v = row[j];
        float4 c = sc[j];
        s0 = fmaf(v.x, c.x, s0);
        s1 = fmaf(v.y, c.y, s1);
        s2 = fmaf(v.z, c.z, s2);
        s3 = fmaf(v.w, c.w, s3);
    }
    float s = __fadd_rn(__fadd_rn(s0, s2), __fadd_rn(s1, s3));
    g_points0[r] = __fadd_rn(mean[r], s);
}

// ---------------------------------------------------------------------------
// K2: keypoints -> pk2 + loss_k/loss_k1 — SMALL-path lowering:
//     transform = nofma-left (VERIFIED out6=0), projection = nofma + recip
// ---------------------------------------------------------------------------
__global__ void k_key(const int*   __restrict__ key_keypoint,
                      const float* __restrict__ key_ref,
                      const float* __restrict__ key_side_ref,
                      const float* __restrict__ T,
                      float* __restrict__ out)
{
    __shared__ double s_in[256];
    __shared__ double s_sd[256];
    int t = threadIdx.x;
    double accI = 0.0, accS = 0.0;

    for (int i = t; i < BB * NUMK; i += 256) {
        int b = i / NUMK, k = i % NUMK;
        int idx = key_keypoint[k];
        float px = g_points0[3*idx+0];
        float py = g_points0[3*idx+1];
        float pz = g_points0[3*idx+2];
        const float* r = &g_R1[b*9];
        float qx = __fadd_rn(dot3_nofma_left(px, py, pz, r[0], r[3], r[6]), T[b*3+0]);
        float qy = __fadd_rn(dot3_nofma_left(px, py, pz, r[1], r[4], r[7]), T[b*3+1]);
        float qz = __fadd_rn(dot3_nofma_left(px, py, pz, r[2], r[5], r[8]), T[b*3+2]);
        float x, y;
        project_recip_nofma(qx, qy, qz, x, y);
        out[OUT_PK2 + i*2 + 0] = x;
        out[OUT_PK2 + i*2 + 1] = y;

        if (k == 8 || k >= 17) {                      // INNER
            int ii = (k == 8) ? 0 : (k - 16);
            float dx = x - key_ref[(b*52 + ii)*2 + 0];
            float dy = y - key_ref[(b*52 + ii)*2 + 1];
            accI += (double)(dx*dx) + (double)(dy*dy);
        } else {                                      // SIDE
            int si = (k < 8) ? k : (k - 1);
            float dx = x - key_side_ref[(b*16 + si)*2 + 0];
            float dy = y - key_side_ref[(b*16 + si)*2 + 1];
            accS += (double)(dx*dx) + (double)(dy*dy);
        }
    }
    s_in[t] = accI; s_sd[t] = accS;
    __syncthreads();
    for (int o = 128; o > 0; o >>= 1) {
        if (t < o) { s_in[t] += s_in[t+o]; s_sd[t] += s_sd[t+o]; }
        __syncthreads();
    }
    if (t == 0) {
        out[OUT_LK]  = (float)(s_in[0] / (double)(BB*52*2));
        out[OUT_LK1] = (float)(s_sd[0] / (double)(BB*16*2));
    }
}

// ---------------------------------------------------------------------------
// K3 (gates out8): LARGE-path lowering — transform = ASC-FMA (Eigen gemm)
//     + separate rn(+T), projection = nofma + recip-mul
// ---------------------------------------------------------------------------
__global__ void k_scatter(const float* __restrict__ T)
{
    __shared__ float sR[9];
    __shared__ float sT[3];
    int b = blockIdx.y;
    int t = threadIdx.x;
    if (t < 9) sR[t] = g_R1[b*9 + t];
    if (t < 3) sT[t] = T[b*3 + t];
    __syncthreads();

    int n = blockIdx.x * blockDim.x + t;
    if (n >= NUMP) return;

    float px = g_points0[3*n+0];
    float py = g_points0[3*n+1];
    float pz = g_points0[3*n+2];
    float qx = __fadd_rn(dot3_fma_asc(px, py, pz, sR[0], sR[3], sR[6]), sT[0]);
    float qy = __fadd_rn(dot3_fma_asc(px, py, pz, sR[1], sR[4], sR[7]), sT[1]);
    float qz = __fadd_rn(dot3_fma_asc(px, py, pz, sR[2], sR[5], sR[8]), sT[2]);
    float x, y;
    project_recip_nofma(qx, qy, qz, x, y);

    bool m0 = (y >= 0.0f) && (y <= (float)(HIMG-1)) &&
              (x >= 0.0f) && (x <= (float)(WIMG-1));
    int xi = 0, yi = 0;
    if (m0) { xi = (int)x; yi = (int)y; }     // trunc == reference astype(int32)
    g_occ[b*NPIX + yi*WIMG + xi] = 1;

    if (n == 26574) g_y26574[b] = m0 ? y : 0.0f;
}

// ---------------------------------------------------------------------------
// K4: depth pass -> mask & pred_d outputs + per-batch sum/count
// ---------------------------------------------------------------------------
__global__ void k_depth(const float* __restrict__ ref_depth,
                        float* __restrict__ out)
{
    int b   = blockIdx.y;
    int pix = blockIdx.x * 256 + threadIdx.x;     // 900*256 == NPIX exactly

    float yb   = g_y26574[b];
    float dval = g_dval;

    unsigned char occ = g_occ[b*NPIX + pix];
    float ref  = ref_depth[b*NPIX + pix];
    float mf   = occ ? 1.0f : 0.0f;
    float pred = __fmul_rn(yb, mf);
    float refm = __fmul_rn(ref, mf);
    float diff = __fsub_rn(pred, refm);
    float ld   = __fmul_rn(diff, diff);
    bool  mk   = (ld < dval) && (ld > 1e-6f) && (pred > 0.0f);
    float ld2  = ((ld > dval) || (pred < 1e-5f)) ? 0.0f : ld;

    out[OUT_MASK + b*NPIX + pix] = mk ? 1.0f : 0.0f;
    out[OUT_PRED + b*NPIX + pix] = pred;

    __shared__ double sd[256];
    __shared__ int    si[256];
    sd[threadIdx.x] = (double)ld2;
    si[threadIdx.x] = mk ? 1 : 0;
    __syncthreads();
    for (int o = 128; o > 0; o >>= 1) {
        if (threadIdx.x < o) { sd[threadIdx.x] += sd[threadIdx.x+o]; si[threadIdx.x] += si[threadIdx.x+o]; }
        __syncthreads();
    }
    if (threadIdx.x == 0) {
        atomicAdd(&g_sum[b], sd[0]);
        atomicAdd(&g_cnt[b], si[0]);
    }
}

// ---------------------------------------------------------------------------
// K5: loss_d = mean_b( sum_b / (cnt_b + 1) )
// ---------------------------------------------------------------------------
__global__ void k_final(float* __restrict__ out)
{
    int t = threadIdx.x;
    double v = 0.0;
    if (t < BB) v = g_sum[t] / ((double)g_cnt[t] + 1.0);
    #pragma unroll
    for (int o = 16; o > 0; o >>= 1) v += __shfl_down_sync(0xffffffffu, v, o);
    if (t == 0) out[OUT_LD] = (float)(v / (double)BB);
}

// ---------------------------------------------------------------------------
extern "C" void kernel_launch(void* const* d_in, const int* in_sizes, int n_in,
                              void* d_out, int out_size)
{
    const float*    mean         = (const float*)d_in[0];
    const float*    pca          = (const float*)d_in[1];
    const float*    variance     = (const float*)d_in[2];
    const float*    param        = (const float*)d_in[3];
    const float*    R            = (const float*)d_in[4];
    const float*    T            = (const float*)d_in[5];
    const int*      key_keypoint = (const int*)d_in[6];
    const float*    key_ref      = (const float*)d_in[7];
    const float*    key_side_ref = (const float*)d_in[8];
    const float*    ref_depth    = (const float*)d_in[9];
    const unsigned* dptr         = (const unsigned*)d_in[10];
    float* out = (float*)d_out;

    // K0: init (zero 3.7MB occ as uint4 + scalars)
    k_init<<<(BB*NPIX/16 + 255)/256, 256>>>(variance, param, R, T, dptr, out);

    // K1: PCA matvec, thread per row
    k_points0<<<(ROWS + 255)/256, 256>>>(mean, pca);

    // K2: keypoints + loss_k/loss_k1 (small-path chain: nofma-left)
    k_key<<<1, 256>>>(key_keypoint, key_ref, key_side_ref, T, out);

    // K3: scatter occupancy (large-path chain: asc-FMA transform)
    dim3 gs((NUMP + 255)/256, BB);
    k_scatter<<<gs, 256>>>(T);

    // K4: depth image pass
    dim3 gd(NPIX/256, BB);
    k_depth<<<gd, 256>>>(ref_depth, out);

    // K5: finalize loss_d
    k_final<<<1, 32>>>(out);
}

// round 16
// speedup vs baseline: 1.1796x; 1.1796x over previous
#include <cuda_runtime.h>
#include <math.h>

#define NUMP 53149
#define NUMK 68
#define KPCA 80
#define BB   16
#define HIMG 640
#define WIMG 360
#define NPIX (HIMG*WIMG)          // 230400
#define ROWS (3*NUMP)             // 159447

// output layout (float32 concat of the returned tuple)
#define OUT_LK   0
#define OUT_LK1  1
#define OUT_LREG 2
#define OUT_LD   3
#define OUT_R1   4                 // B*9 = 144
#define OUT_T    148               // B*3 = 48
#define OUT_PK2  196               // B*68*2 = 2176
#define OUT_MASK 2372              // B*NPIX   (2372*4 % 16 == 0: float4-aligned)
#define OUT_PRED (2372 + BB*NPIX)  // B*NPIX   (also float4-aligned)

__device__ float          g_points0[ROWS];
__device__ unsigned char  g_occ[BB*NPIX];
__device__ float          g_coef[KPCA];
__device__ float          g_R1[BB*9];
__device__ float          g_y26574[BB];
__device__ double         g_sum[BB];
__device__ int            g_cnt[BB];
__device__ float          g_dval;

// correctly-rounded f32 trig (verified: R1 bit-exact with these)
__device__ __forceinline__ float sinf_cr(float x) { return (float)sin((double)x); }
__device__ __forceinline__ float cosf_cr(float x) { return (float)cos((double)x); }

// asc-k FMA dot from zero — VERIFIED large-path transform + R1 3x3 chain
__device__ __forceinline__ float dot3_fma_asc(float a0, float a1, float a2,
                                              float b0, float b1, float b2)
{
    return fmaf(a2, b2, fmaf(a1, b1, __fmul_rn(a0, b0)));
}

// nofma LEFT-assoc — VERIFIED small-path (pk) transform chain
__device__ __forceinline__ float dot3_nofma_left(float a0, float a1, float a2,
                                                 float b0, float b1, float b2)
{
    return __fadd_rn(__fadd_rn(__fmul_rn(a0, b0), __fmul_rn(a1, b1)),
                     __fmul_rn(a2, b2));
}

// VERIFIED projection: nofma numerators + RECIP-MUL divide
__device__ __forceinline__ void project_recip_nofma(float qx, float qy, float qz,
                                                    float& x, float& y)
{
    float pz  = -qz;
    float inv = __frcp_rn(pz);
    float ax  = __fadd_rn(__fmul_rn(qx, 436.16f), __fmul_rn(pz, 179.22f));
    float ay  = __fadd_rn(__fmul_rn(qy, 436.16f), __fmul_rn(pz, 320.08f));
    x = __fmul_rn(ax, inv);
    y = __fmul_rn(ay, inv);
}

// ---------------------------------------------------------------------------
// K0: zero occupancy map; compute coef, R1 (bit-exact), loss_reg; T; parse d
// ---------------------------------------------------------------------------
__global__ void k_init(const float* __restrict__ variance,
                       const float* __restrict__ param,
                       const float* __restrict__ R,
                       const float* __restrict__ T,
                       const unsigned* __restrict__ dptr,
                       float* __restrict__ out)
{
    int gid = blockIdx.x * blockDim.x + threadIdx.x;
    if (gid < (BB*NPIX)/16) ((uint4*)g_occ)[gid] = make_uint4(0u,0u,0u,0u);

    if (blockIdx.x == 0) {
        int t = threadIdx.x;
        if (t < KPCA) g_coef[t] = __fmul_rn(param[t], sqrtf(variance[t]));
        if (t >= 128 && t < 128 + BB) {
            int b = t - 128;
            float ax = R[b*3+0], ay = R[b*3+1], az = R[b*3+2];
            float sx = sinf_cr(ax), cx = cosf_cr(ax);
            float sy = sinf_cr(ay), cy = cosf_cr(ay);
            float sz = sinf_cr(az), cz = cosf_cr(az);
            float Rz[9] = { cz, -sz, 0.f,  sz,  cz, 0.f,  0.f, 0.f, 1.f };
            float Ry[9] = { cy, 0.f,  sy,  0.f, 1.f, 0.f, -sy, 0.f,  cy };
            float Rx[9] = { 1.f, 0.f, 0.f, 0.f,  cx, -sx,  0.f,  sx,  cx };
            float M1[9], r[9];
            #pragma unroll
            for (int i = 0; i < 3; ++i)
                #pragma unroll
                for (int j = 0; j < 3; ++j)
                    M1[i*3+j] = dot3_fma_asc(Rz[i*3+0], Rz[i*3+1], Rz[i*3+2],
                                             Ry[0*3+j], Ry[1*3+j], Ry[2*3+j]);
            #pragma unroll
            for (int i = 0; i < 3; ++i)
                #pragma unroll
                for (int j = 0; j < 3; ++j)
                    r[i*3+j] = dot3_fma_asc(M1[i*3+0], M1[i*3+1], M1[i*3+2],
                                            Rx[0*3+j], Rx[1*3+j], Rx[2*3+j]);
            #pragma unroll
            for (int i = 0; i < 9; ++i) {
                g_R1[b*9+i] = r[i];
                out[OUT_R1 + b*9 + i] = r[i];
            }
            g_sum[b] = 0.0;
            g_cnt[b] = 0;
        }
        if (t >= 160 && t < 160 + BB*3) out[OUT_T + (t - 160)] = T[t - 160];
        if (t == 224) {
            double s = 0.0;
            for (int i = 0; i < KPCA; ++i) { double p = (double)param[i]; s += p*p; }
            out[OUT_LREG] = (float)(s / (double)KPCA);
        }
        if (t == 225) {
            unsigned raw = *dptr;              // works for int32(100) or float32(100.f)
            g_dval = (raw == 100u) ? 100.0f : __uint_as_float(raw);
        }
    }
}

// ---------------------------------------------------------------------------
// K1: points0 = mean + pca @ coef — smem-staged coalesced tiles.
//     FP ops identical to the verified variant: 4 FMA lanes (k mod 4),
//     reduce (s0+s2)+(s1+s3), then rn(+mean).
// ---------------------------------------------------------------------------
#define RPB 128                      // rows per block
__global__ void k_points0(const float* __restrict__ mean,
                          const float* __restrict__ pca)
{
    __shared__ float4 tile[RPB * (KPCA/4)];   // 128 rows x 320B = 40KB
    __shared__ float4 sc[KPCA/4];
    int t = threadIdx.x;                      // 128 threads
    if (t < KPCA/4) sc[t] = ((const float4*)g_coef)[t];

    int row0 = blockIdx.x * RPB;
    const float4* src = (const float4*)pca + (size_t)row0 * (KPCA/4);
    #pragma unroll
    for (int i = 0; i < RPB * (KPCA/4) / RPB; ++i) {   // 20 iters, stride 128
        int idx = i * RPB + t;
        int r = row0 + idx / (KPCA/4);
        if (r < ROWS) tile[idx] = src[idx];
    }
    __syncthreads();

    int r = row0 + t;
    if (r >= ROWS) return;

    const float4* row = &tile[t * (KPCA/4)];
    float s0 = 0.f, s1 = 0.f, s2 = 0.f, s3 = 0.f;
    #pragma unroll
    for (int j = 0; j < KPCA/4; ++j) {
        float4 v = row[j];
        float4 c = sc[j];
        s0 = fmaf(v.x, c.x, s0);
        s1 = fmaf(v.y, c.y, s1);
        s2 = fmaf(v.z, c.z, s2);
        s3 = fmaf(v.w, c.w, s3);
    }
    float s = __fadd_rn(__fadd_rn(s0, s2), __fadd_rn(s1, s3));
    g_points0[r] = __fadd_rn(mean[r], s);
}

// ---------------------------------------------------------------------------
// K2: keypoints -> pk2 + loss_k/loss_k1 — VERIFIED small-path chain
// ---------------------------------------------------------------------------
__global__ void k_key(const int*   __restrict__ key_keypoint,
                      const float* __restrict__ key_ref,
                      const float* __restrict__ key_side_ref,
                      const float* __restrict__ T,
                      float* __restrict__ out)
{
    __shared__ double s_in[256];
    __shared__ double s_sd[256];
    int t = threadIdx.x;
    double accI = 0.0, accS = 0.0;

    for (int i = t; i < BB * NUMK; i += 256) {
        int b = i / NUMK, k = i % NUMK;
        int idx = key_keypoint[k];
        float px = g_points0[3*idx+0];
        float py = g_points0[3*idx+1];
        float pz = g_points0[3*idx+2];
        const float* r = &g_R1[b*9];
        float qx = __fadd_rn(dot3_nofma_left(px, py, pz, r[0], r[3], r[6]), T[b*3+0]);
        float qy = __fadd_rn(dot3_nofma_left(px, py, pz, r[1], r[4], r[7]), T[b*3+1]);
        float qz = __fadd_rn(dot3_nofma_left(px, py, pz, r[2], r[5], r[8]), T[b*3+2]);
        float x, y;
        project_recip_nofma(qx, qy, qz, x, y);
        out[OUT_PK2 + i*2 + 0] = x;
        out[OUT_PK2 + i*2 + 1] = y;

        if (k == 8 || k >= 17) {                      // INNER
            int ii = (k == 8) ? 0 : (k - 16);
            float dx = x - key_ref[(b*52 + ii)*2 + 0];
            float dy = y - key_ref[(b*52 + ii)*2 + 1];
            accI += (double)(dx*dx) + (double)(dy*dy);
        } else {                                      // SIDE
            int si = (k < 8) ? k : (k - 1);
            float dx = x - key_side_ref[(b*16 + si)*2 + 0];
            float dy = y - key_side_ref[(b*16 + si)*2 + 1];
            accS += (double)(dx*dx) + (double)(dy*dy);
        }
    }
    s_in[t] = accI; s_sd[t] = accS;
    __syncthreads();
    for (int o = 128; o > 0; o >>= 1) {
        if (t < o) { s_in[t] += s_in[t+o]; s_sd[t] += s_sd[t+o]; }
        __syncthreads();
    }
    if (t == 0) {
        out[OUT_LK]  = (float)(s_in[0] / (double)(BB*52*2));
        out[OUT_LK1] = (float)(s_sd[0] / (double)(BB*16*2));
    }
}

// ---------------------------------------------------------------------------
// K3: scatter — batch loop inside thread (load point ONCE, 16 transforms).
//     VERIFIED large-path chain: asc-FMA transform + nofma-P + recip-mul.
// ---------------------------------------------------------------------------
__global__ void k_scatter(const float* __restrict__ T)
{
    __shared__ float sR[BB*9];
    __shared__ float sT[BB*3];
    int t = threadIdx.x;
    if (t < BB*9) sR[t] = g_R1[t];
    if (t < BB*3) sT[t] = T[t];
    __syncthreads();

    int n = blockIdx.x * blockDim.x + t;
    if (n >= NUMP) return;

    float px = g_points0[3*n+0];
    float py = g_points0[3*n+1];
    float pz = g_points0[3*n+2];
    bool is_probe = (n == 26574);

    #pragma unroll 4
    for (int b = 0; b < BB; ++b) {
        const float* r = &sR[b*9];
        float qx = __fadd_rn(dot3_fma_asc(px, py, pz, r[0], r[3], r[6]), sT[b*3+0]);
        float qy = __fadd_rn(dot3_fma_asc(px, py, pz, r[1], r[4], r[7]), sT[b*3+1]);
        float qz = __fadd_rn(dot3_fma_asc(px, py, pz, r[2], r[5], r[8]), sT[b*3+2]);
        float x, y;
        project_recip_nofma(qx, qy, qz, x, y);

        bool m0 = (y >= 0.0f) && (y <= (float)(HIMG-1)) &&
                  (x >= 0.0f) && (x <= (float)(WIMG-1));
        int xi = 0, yi = 0;
        if (m0) { xi = (int)x; yi = (int)y; }
        g_occ[b*NPIX + yi*WIMG + xi] = 1;

        if (is_probe) g_y26574[b] = m0 ? y : 0.0f;
    }
}

// ---------------------------------------------------------------------------
// K4: depth pass — 4 pixels/thread (float4/uchar4), warp-shuffle dbl reduce
// ---------------------------------------------------------------------------
__global__ void k_depth(const float* __restrict__ ref_depth,
                        float* __restrict__ out)
{
    int b  = blockIdx.y;
    int i4 = blockIdx.x * 256 + threadIdx.x;      // float4 index; 225*256 = 57600 = NPIX/4

    float yb   = g_y26574[b];
    float dval = g_dval;

    uchar4 oc = ((const uchar4*)(g_occ + b*NPIX))[i4];
    float4 rf = ((const float4*)(ref_depth + (size_t)b*NPIX))[i4];

    float4 mk4, pd4;
    double acc = 0.0;
    int    cnt = 0;
    {
        unsigned char occs[4] = { oc.x, oc.y, oc.z, oc.w };
        float refs[4] = { rf.x, rf.y, rf.z, rf.w };
        float mks[4], pds[4];
        #pragma unroll
        for (int j = 0; j < 4; ++j) {
            float mf   = occs[j] ? 1.0f : 0.0f;
            float pred = __fmul_rn(yb, mf);
            float refm = __fmul_rn(refs[j], mf);
            float diff = __fsub_rn(pred, refm);
            float ld   = __fmul_rn(diff, diff);
            bool  mk   = (ld < dval) && (ld > 1e-6f) && (pred > 0.0f);
            float ld2  = ((ld > dval) || (pred < 1e-5f)) ? 0.0f : ld;
            mks[j] = mk ? 1.0f : 0.0f;
            pds[j] = pred;
            acc += (double)ld2;
            cnt += mk ? 1 : 0;
        }
        mk4 = make_float4(mks[0], mks[1], mks[2], mks[3]);
        pd4 = make_float4(pds[0], pds[1], pds[2], pds[3]);
    }

    ((float4*)(out + OUT_MASK + (size_t)b*NPIX))[i4] = mk4;
    ((float4*)(out + OUT_PRED + (size_t)b*NPIX))[i4] = pd4;

    // warp reduce (double + int), one atomic per warp
    #pragma unroll
    for (int o = 16; o > 0; o >>= 1) {
        acc += __shfl_down_sync(0xffffffffu, acc, o);
        cnt += __shfl_down_sync(0xffffffffu, cnt, o);
    }
    if ((threadIdx.x & 31) == 0) {
        atomicAdd(&g_sum[b], acc);
        atomicAdd(&g_cnt[b], cnt);
    }
}

// ---------------------------------------------------------------------------
// K5: loss_d = mean_b( sum_b / (cnt_b + 1) )
// ---------------------------------------------------------------------------
__global__ void k_final(float* __restrict__ out)
{
    int t = threadIdx.x;
    double v = 0.0;
    if (t < BB) v = g_sum[t] / ((double)g_cnt[t] + 1.0);
    #pragma unroll
    for (int o = 16; o > 0; o >>= 1) v += __shfl_down_sync(0xffffffffu, v, o);
    if (t == 0) out[OUT_LD] = (float)(v / (double)BB);
}

// ---------------------------------------------------------------------------
extern "C" void kernel_launch(void* const* d_in, const int* in_sizes, int n_in,
                              void* d_out, int out_size)
{
    const float*    mean         = (const float*)d_in[0];
    const float*    pca          = (const float*)d_in[1];
    const float*    variance     = (const float*)d_in[2];
    const float*    param        = (const float*)d_in[3];
    const float*    R            = (const float*)d_in[4];
    const float*    T            = (const float*)d_in[5];
    const int*      key_keypoint = (const int*)d_in[6];
    const float*    key_ref      = (const float*)d_in[7];
    const float*    key_side_ref = (const float*)d_in[8];
    const float*    ref_depth    = (const float*)d_in[9];
    const unsigned* dptr         = (const unsigned*)d_in[10];
    float* out = (float*)d_out;

    // K0: init (zero 3.7MB occ as uint4 + scalars)
    k_init<<<(BB*NPIX/16 + 255)/256, 256>>>(variance, param, R, T, dptr, out);

    // K1: PCA matvec, smem-staged coalesced, 128 rows/block
    k_points0<<<(ROWS + RPB - 1)/RPB, RPB>>>(mean, pca);

    // K2: keypoints + loss_k/loss_k1
    k_key<<<1, 256>>>(key_keypoint, key_ref, key_side_ref, T, out);

    // K3: scatter occupancy — batch loop inside thread
    k_scatter<<<(NUMP + 255)/256, 256>>>(T);

    // K4: depth image pass — 4 px/thread
    dim3 gd(NPIX/(256*4), BB);
    k_depth<<<gd, 256>>>(ref_depth, out);

    // K5: finalize loss_d
    k_final<<<1, 32>>>(out);
}

// round 17
// speedup vs baseline: 1.2629x; 1.0706x over previous
#include <cuda_runtime.h>
#include <math.h>

#define NUMP 53149
#define NUMK 68
#define KPCA 80
#define BB   16
#define HIMG 640
#define WIMG 360
#define NPIX (HIMG*WIMG)          // 230400
#define ROWS (3*NUMP)             // 159447

// output layout (float32 concat of the returned tuple)
#define OUT_LK   0
#define OUT_LK1  1
#define OUT_LREG 2
#define OUT_LD   3
#define OUT_R1   4                 // B*9 = 144
#define OUT_T    148               // B*3 = 48
#define OUT_PK2  196               // B*68*2 = 2176
#define OUT_MASK 2372              // B*NPIX   (2372*4 % 16 == 0: float4-aligned)
#define OUT_PRED (2372 + BB*NPIX)  // B*NPIX   (also float4-aligned)

__device__ float          g_points0[ROWS];
__device__ unsigned char  g_occ[BB*NPIX];
__device__ float          g_coef[KPCA];
__device__ float          g_R1[BB*9];
__device__ float          g_y26574[BB];
__device__ double         g_sum[BB];
__device__ int            g_cnt[BB];
__device__ float          g_dval;

// correctly-rounded f32 trig (verified: R1 bit-exact with these)
__device__ __forceinline__ float sinf_cr(float x) { return (float)sin((double)x); }
__device__ __forceinline__ float cosf_cr(float x) { return (float)cos((double)x); }

// asc-k FMA dot from zero — VERIFIED large-path transform + R1 3x3 chain
__device__ __forceinline__ float dot3_fma_asc(float a0, float a1, float a2,
                                              float b0, float b1, float b2)
{
    return fmaf(a2, b2, fmaf(a1, b1, __fmul_rn(a0, b0)));
}

// nofma LEFT-assoc — VERIFIED small-path (pk) transform chain
__device__ __forceinline__ float dot3_nofma_left(float a0, float a1, float a2,
                                                 float b0, float b1, float b2)
{
    return __fadd_rn(__fadd_rn(__fmul_rn(a0, b0), __fmul_rn(a1, b1)),
                     __fmul_rn(a2, b2));
}

// VERIFIED projection: nofma numerators + RECIP-MUL divide
__device__ __forceinline__ void project_recip_nofma(float qx, float qy, float qz,
                                                    float& x, float& y)
{
    float pz  = -qz;
    float inv = __frcp_rn(pz);
    float ax  = __fadd_rn(__fmul_rn(qx, 436.16f), __fmul_rn(pz, 179.22f));
    float ay  = __fadd_rn(__fmul_rn(qy, 436.16f), __fmul_rn(pz, 320.08f));
    x = __fmul_rn(ax, inv);
    y = __fmul_rn(ay, inv);
}

// ---------------------------------------------------------------------------
// K0: zero occupancy map; compute coef, R1 (bit-exact), loss_reg; T; parse d
// ---------------------------------------------------------------------------
__global__ void k_init(const float* __restrict__ variance,
                       const float* __restrict__ param,
                       const float* __restrict__ R,
                       const float* __restrict__ T,
                       const unsigned* __restrict__ dptr,
                       float* __restrict__ out)
{
    int gid = blockIdx.x * blockDim.x + threadIdx.x;
    if (gid < (BB*NPIX)/16) ((uint4*)g_occ)[gid] = make_uint4(0u,0u,0u,0u);

    if (blockIdx.x == 0) {
        int t = threadIdx.x;
        if (t < KPCA) g_coef[t] = __fmul_rn(param[t], sqrtf(variance[t]));
        if (t >= 128 && t < 128 + BB) {
            int b = t - 128;
            float ax = R[b*3+0], ay = R[b*3+1], az = R[b*3+2];
            float sx = sinf_cr(ax), cx = cosf_cr(ax);
            float sy = sinf_cr(ay), cy = cosf_cr(ay);
            float sz = sinf_cr(az), cz = cosf_cr(az);
            float Rz[9] = { cz, -sz, 0.f,  sz,  cz, 0.f,  0.f, 0.f, 1.f };
            float Ry[9] = { cy, 0.f,  sy,  0.f, 1.f, 0.f, -sy, 0.f,  cy };
            float Rx[9] = { 1.f, 0.f, 0.f, 0.f,  cx, -sx,  0.f,  sx,  cx };
            float M1[9], r[9];
            #pragma unroll
            for (int i = 0; i < 3; ++i)
                #pragma unroll
                for (int j = 0; j < 3; ++j)
                    M1[i*3+j] = dot3_fma_asc(Rz[i*3+0], Rz[i*3+1], Rz[i*3+2],
                                             Ry[0*3+j], Ry[1*3+j], Ry[2*3+j]);
            #pragma unroll
            for (int i = 0; i < 3; ++i)
                #pragma unroll
                for (int j = 0; j < 3; ++j)
                    r[i*3+j] = dot3_fma_asc(M1[i*3+0], M1[i*3+1], M1[i*3+2],
                                            Rx[0*3+j], Rx[1*3+j], Rx[2*3+j]);
            #pragma unroll
            for (int i = 0; i < 9; ++i) {
                g_R1[b*9+i] = r[i];
                out[OUT_R1 + b*9 + i] = r[i];
            }
            g_sum[b] = 0.0;
            g_cnt[b] = 0;
        }
        if (t >= 160 && t < 160 + BB*3) out[OUT_T + (t - 160)] = T[t - 160];
        if (t == 224) {
            double s = 0.0;
            for (int i = 0; i < KPCA; ++i) { double p = (double)param[i]; s += p*p; }
            out[OUT_LREG] = (float)(s / (double)KPCA);
        }
        if (t == 225) {
            unsigned raw = *dptr;              // works for int32(100) or float32(100.f)
            g_dval = (raw == 100u) ? 100.0f : __uint_as_float(raw);
        }
    }
}

// ---------------------------------------------------------------------------
// K1: points0 = mean + pca @ coef — smem-staged coalesced tiles.
//     FP ops identical to the verified variant: 4 FMA lanes (k mod 4),
//     reduce (s0+s2)+(s1+s3), then rn(+mean).
// ---------------------------------------------------------------------------
#define RPB 128                      // rows per block
__global__ void k_points0(const float* __restrict__ mean,
                          const float* __restrict__ pca)
{
    __shared__ float4 tile[RPB * (KPCA/4)];   // 128 rows x 320B = 40KB
    __shared__ float4 sc[KPCA/4];
    int t = threadIdx.x;                      // 128 threads
    if (t < KPCA/4) sc[t] = ((const float4*)g_coef)[t];

    int row0 = blockIdx.x * RPB;
    const float4* src = (const float4*)pca + (size_t)row0 * (KPCA/4);
    #pragma unroll
    for (int i = 0; i < (KPCA/4); ++i) {      // 20 iters, stride 128
        int idx = i * RPB + t;
        int r = row0 + idx / (KPCA/4);
        if (r < ROWS) tile[idx] = src[idx];
    }
    __syncthreads();

    int r = row0 + t;
    if (r >= ROWS) return;

    const float4* row = &tile[t * (KPCA/4)];
    float s0 = 0.f, s1 = 0.f, s2 = 0.f, s3 = 0.f;
    #pragma unroll
    for (int j = 0; j < KPCA/4; ++j) {
        float4 v = row[j];
        float4 c = sc[j];
        s0 = fmaf(v.x, c.x, s0);
        s1 = fmaf(v.y, c.y, s1);
        s2 = fmaf(v.z, c.z, s2);
        s3 = fmaf(v.w, c.w, s3);
    }
    float s = __fadd_rn(__fadd_rn(s0, s2), __fadd_rn(s1, s3));
    g_points0[r] = __fadd_rn(mean[r], s);
}

// ---------------------------------------------------------------------------
// key-loss body (runs as one block inside k_scatter's extra grid.y slice)
// VERIFIED small-path chain: nofma-left transform + nofma-P + recip-mul
// ---------------------------------------------------------------------------
__device__ void key_body(const int*   __restrict__ key_keypoint,
                         const float* __restrict__ key_ref,
                         const float* __restrict__ key_side_ref,
                         const float* __restrict__ T,
                         float* __restrict__ out)
{
    __shared__ double s_in[256];
    __shared__ double s_sd[256];
    int t = threadIdx.x;
    double accI = 0.0, accS = 0.0;

    for (int i = t; i < BB * NUMK; i += 256) {
        int b = i / NUMK, k = i % NUMK;
        int idx = key_keypoint[k];
        float px = g_points0[3*idx+0];
        float py = g_points0[3*idx+1];
        float pz = g_points0[3*idx+2];
        const float* r = &g_R1[b*9];
        float qx = __fadd_rn(dot3_nofma_left(px, py, pz, r[0], r[3], r[6]), T[b*3+0]);
        float qy = __fadd_rn(dot3_nofma_left(px, py, pz, r[1], r[4], r[7]), T[b*3+1]);
        float qz = __fadd_rn(dot3_nofma_left(px, py, pz, r[2], r[5], r[8]), T[b*3+2]);
        float x, y;
        project_recip_nofma(qx, qy, qz, x, y);
        out[OUT_PK2 + i*2 + 0] = x;
        out[OUT_PK2 + i*2 + 1] = y;

        if (k == 8 || k >= 17) {                      // INNER
            int ii = (k == 8) ? 0 : (k - 16);
            float dx = x - key_ref[(b*52 + ii)*2 + 0];
            float dy = y - key_ref[(b*52 + ii)*2 + 1];
            accI += (double)(dx*dx) + (double)(dy*dy);
        } else {                                      // SIDE
            int si = (k < 8) ? k : (k - 1);
            float dx = x - key_side_ref[(b*16 + si)*2 + 0];
            float dy = y - key_side_ref[(b*16 + si)*2 + 1];
            accS += (double)(dx*dx) + (double)(dy*dy);
        }
    }
    s_in[t] = accI; s_sd[t] = accS;
    __syncthreads();
    for (int o = 128; o > 0; o >>= 1) {
        if (t < o) { s_in[t] += s_in[t+o]; s_sd[t] += s_sd[t+o]; }
        __syncthreads();
    }
    if (t == 0) {
        out[OUT_LK]  = (float)(s_in[0] / (double)(BB*52*2));
        out[OUT_LK1] = (float)(s_sd[0] / (double)(BB*16*2));
    }
}

// ---------------------------------------------------------------------------
// K3: scatter — 2 batches per thread, grid.y=8 (occupancy) + key slice (y=8).
//     VERIFIED large-path chain: asc-FMA transform + nofma-P + recip-mul.
// ---------------------------------------------------------------------------
__global__ void k_scatter(const float* __restrict__ T,
                          const int*   __restrict__ key_keypoint,
                          const float* __restrict__ key_ref,
                          const float* __restrict__ key_side_ref,
                          float* __restrict__ out)
{
    if (blockIdx.y == BB/2) {                 // extra slice: keypoint losses
        if (blockIdx.x == 0)
            key_body(key_keypoint, key_ref, key_side_ref, T, out);
        return;
    }

    __shared__ float sR[2*9];
    __shared__ float sT[2*3];
    int t  = threadIdx.x;
    int b0 = blockIdx.y * 2;
    if (t < 2*9) sR[t] = g_R1[b0*9 + t];
    if (t < 2*3) sT[t] = T[b0*3 + t];
    __syncthreads();

    int n = blockIdx.x * blockDim.x + t;
    if (n >= NUMP) return;

    float px = g_points0[3*n+0];
    float py = g_points0[3*n+1];
    float pz = g_points0[3*n+2];
    bool is_probe = (n == 26574);

    #pragma unroll
    for (int j = 0; j < 2; ++j) {
        int b = b0 + j;
        const float* r = &sR[j*9];
        float qx = __fadd_rn(dot3_fma_asc(px, py, pz, r[0], r[3], r[6]), sT[j*3+0]);
        float qy = __fadd_rn(dot3_fma_asc(px, py, pz, r[1], r[4], r[7]), sT[j*3+1]);
        float qz = __fadd_rn(dot3_fma_asc(px, py, pz, r[2], r[5], r[8]), sT[j*3+2]);
        float x, y;
        project_recip_nofma(qx, qy, qz, x, y);

        bool m0 = (y >= 0.0f) && (y <= (float)(HIMG-1)) &&
                  (x >= 0.0f) && (x <= (float)(WIMG-1));
        int xi = 0, yi = 0;
        if (m0) { xi = (int)x; yi = (int)y; }
        g_occ[b*NPIX + yi*WIMG + xi] = 1;

        if (is_probe) g_y26574[b] = m0 ? y : 0.0f;
    }
}

// ---------------------------------------------------------------------------
// K4: depth pass — 4 pixels/thread (float4/uchar4), warp-shuffle dbl reduce
// ---------------------------------------------------------------------------
__global__ void k_depth(const float* __restrict__ ref_depth,
                        float* __restrict__ out)
{
    int b  = blockIdx.y;
    int i4 = blockIdx.x * 256 + threadIdx.x;      // float4 index; 225*256 = 57600 = NPIX/4

    float yb   = g_y26574[b];
    float dval = g_dval;

    uchar4 oc = ((const uchar4*)(g_occ + b*NPIX))[i4];
    float4 rf = ((const float4*)(ref_depth + (size_t)b*NPIX))[i4];

    float4 mk4, pd4;
    double acc = 0.0;
    int    cnt = 0;
    {
        unsigned char occs[4] = { oc.x, oc.y, oc.z, oc.w };
        float refs[4] = { rf.x, rf.y, rf.z, rf.w };
        float mks[4], pds[4];
        #pragma unroll
        for (int j = 0; j < 4; ++j) {
            float mf   = occs[j] ? 1.0f : 0.0f;
            float pred = __fmul_rn(yb, mf);
            float refm = __fmul_rn(refs[j], mf);
            float diff = __fsub_rn(pred, refm);
            float ld   = __fmul_rn(diff, diff);
            bool  mk   = (ld < dval) && (ld > 1e-6f) && (pred > 0.0f);
            float ld2  = ((ld > dval) || (pred < 1e-5f)) ? 0.0f : ld;
            mks[j] = mk ? 1.0f : 0.0f;
            pds[j] = pred;
            acc += (double)ld2;
            cnt += mk ? 1 : 0;
        }
        mk4 = make_float4(mks[0], mks[1], mks[2], mks[3]);
        pd4 = make_float4(pds[0], pds[1], pds[2], pds[3]);
    }

    ((float4*)(out + OUT_MASK + (size_t)b*NPIX))[i4] = mk4;
    ((float4*)(out + OUT_PRED + (size_t)b*NPIX))[i4] = pd4;

    // warp reduce (double + int), one atomic per warp
    #pragma unroll
    for (int o = 16; o > 0; o >>= 1) {
        acc += __shfl_down_sync(0xffffffffu, acc, o);
        cnt += __shfl_down_sync(0xffffffffu, cnt, o);
    }
    if ((threadIdx.x & 31) == 0) {
        atomicAdd(&g_sum[b], acc);
        atomicAdd(&g_cnt[b], cnt);
    }
}

// ---------------------------------------------------------------------------
// K5: loss_d = mean_b( sum_b / (cnt_b + 1) )
// ---------------------------------------------------------------------------
__global__ void k_final(float* __restrict__ out)
{
    int t = threadIdx.x;
    double v = 0.0;
    if (t < BB) v = g_sum[t] / ((double)g_cnt[t] + 1.0);
    #pragma unroll
    for (int o = 16; o > 0; o >>= 1) v += __shfl_down_sync(0xffffffffu, v, o);
    if (t == 0) out[OUT_LD] = (float)(v / (double)BB);
}

// ---------------------------------------------------------------------------
extern "C" void kernel_launch(void* const* d_in, const int* in_sizes, int n_in,
                              void* d_out, int out_size)
{
    const float*    mean         = (const float*)d_in[0];
    const float*    pca          = (const float*)d_in[1];
    const float*    variance     = (const float*)d_in[2];
    const float*    param        = (const float*)d_in[3];
    const float*    R            = (const float*)d_in[4];
    const float*    T            = (const float*)d_in[5];
    const int*      key_keypoint = (const int*)d_in[6];
    const float*    key_ref      = (const float*)d_in[7];
    const float*    key_side_ref = (const float*)d_in[8];
    const float*    ref_depth    = (const float*)d_in[9];
    const unsigned* dptr         = (const unsigned*)d_in[10];
    float* out = (float*)d_out;

    // K0: init (zero 3.7MB occ as uint4 + scalars)
    k_init<<<(BB*NPIX/16 + 255)/256, 256>>>(variance, param, R, T, dptr, out);

    // K1: PCA matvec, smem-staged coalesced, 128 rows/block
    k_points0<<<(ROWS + RPB - 1)/RPB, RPB>>>(mean, pca);

    // K3: scatter occupancy (grid.y: 8 batch-pairs + 1 key slice)
    dim3 gs((NUMP + 255)/256, BB/2 + 1);
    k_scatter<<<gs, 256>>>(T, key_keypoint, key_ref, key_side_ref, out);

    // K4: depth image pass — 4 px/thread
    dim3 gd(NPIX/(256*4), BB);
    k_depth<<<gd, 256>>>(ref_depth, out);

    // K5: finalize loss_d
    k_final<<<1, 32>>>(out);
}